// round 15
// baseline (speedup 1.0000x reference)
#include <cuda_runtime.h>
#include <cuda_fp16.h>
#include <cuda_fp8.h>
#include <stdint.h>
#include <math.h>

#define BB 4
#define SS 2048
#define DD 1024
#define M1 (BB*SS)

#define LSCALE 2048.0f
#define LINV   (1.0f/2048.0f)

// ---------------------------------------------------------------------------
// Scratch (device globals).
// ---------------------------------------------------------------------------
__device__ __half  g_xh [(size_t)M1*DD];
__device__ uint8_t g_x8h[(size_t)M1*DD],  g_x8l[(size_t)M1*DD];
__device__ __half  g_Wqh[(size_t)DD*DD],  g_Wkh[(size_t)DD*DD], g_Wvh[(size_t)DD*DD];
__device__ uint8_t g_Wq8h[(size_t)DD*DD], g_Wq8l[(size_t)DD*DD];
__device__ uint8_t g_Wk8h[(size_t)DD*DD], g_Wk8l[(size_t)DD*DD];
__device__ uint8_t g_Wv8h[(size_t)DD*DD];
__device__ float  g_Qf [(size_t)M1*DD];
__device__ float  g_Kf [(size_t)M1*DD];
__device__ float  g_Vf [(size_t)M1*DD];
__device__ __half g_Qh [(size_t)M1*DD];
__device__ __half g_Kh [(size_t)M1*DD];
__device__ __half g_S  [(size_t)BB*SS*SS];

// ---------------------------------------------------------------------------
__device__ __forceinline__ uint32_t s2u(const void* p){
    uint32_t a;
    asm("{ .reg .u64 t; cvta.to.shared.u64 t, %1; cvt.u32.u64 %0, t; }" : "=r"(a) : "l"(p));
    return a;
}
__device__ __forceinline__ uint8_t f2e4m3(float v){
    return (uint8_t)__nv_cvt_float_to_fp8(v, __NV_SATFINITE, __NV_E4M3);
}

#define LDSM4(r0,r1,r2,r3,a) \
    asm volatile("ldmatrix.sync.aligned.m8n8.x4.shared.b16 {%0,%1,%2,%3}, [%4];" \
        : "=r"(r0),"=r"(r1),"=r"(r2),"=r"(r3) : "r"(a))

#define MMAF32(c,a0,a1,a2,a3,b0,b1) \
    asm volatile("mma.sync.aligned.m16n8k16.row.col.f32.f16.f16.f32 " \
        "{%0,%1,%2,%3},{%4,%5,%6,%7},{%8,%9},{%0,%1,%2,%3};" \
        : "+f"((c)[0]),"+f"((c)[1]),"+f"((c)[2]),"+f"((c)[3]) \
        : "r"(a0),"r"(a1),"r"(a2),"r"(a3),"r"(b0),"r"(b1))

#define MMAF16(c,a0,a1,a2,a3,b0,b1) \
    asm volatile("mma.sync.aligned.m16n8k16.row.col.f16.f16.f16.f16 " \
        "{%0,%1},{%2,%3,%4,%5},{%6,%7},{%0,%1};" \
        : "+r"((c)[0]),"+r"((c)[1]) \
        : "r"(a0),"r"(a1),"r"(a2),"r"(a3),"r"(b0),"r"(b1))

// FP8 e4m3 MMA, k32, f32 accumulate
#define MMAQ8(c,a0,a1,a2,a3,b0,b1) \
    asm volatile("mma.sync.aligned.m16n8k32.row.col.f32.e4m3.e4m3.f32 " \
        "{%0,%1,%2,%3},{%4,%5,%6,%7},{%8,%9},{%0,%1,%2,%3};" \
        : "+f"((c)[0]),"+f"((c)[1]),"+f"((c)[2]),"+f"((c)[3]) \
        : "r"(a0),"r"(a1),"r"(a2),"r"(a3),"r"(b0),"r"(b1))

#define CP16(dst,src) \
    asm volatile("cp.async.cg.shared.global [%0], [%1], 16;" :: "r"(dst), "l"(src) : "memory")
#define CP_COMMIT() asm volatile("cp.async.commit_group;" ::: "memory")
#define CP_WAIT1()  asm volatile("cp.async.wait_group 1;" ::: "memory")
#define CP_WAIT0()  asm volatile("cp.async.wait_group 0;" ::: "memory")

// ===========================================================================
// Merged QKV GEMM with FP8 cross terms. CTA 64x64, 128 thr = 4 warps (2x2),
// warp tile 32x32, KC=32, 2-stage cp.async.
// Per output: hi = xh16·Wh16 (f16 k16, f32 acc);
//             cross = x8l·W8h + x8h·W8l (e4m3 k32, f32 acc, scaled 2048).
// V: hi + x8l·Wv8h only. Final: C = hi + cross/2048 + bias.
// smem: f16 tile pitch 80 (5120B), fp8 tile pitch 48 (3072B);
// stage = 3 f16 A?  -> A:{xh16,x8h,x8l} + Q:{h16,8h,8l} + K:{h16,8h,8l} + V:{h16,8h}
//       = 4*5120 + 7*3072 = 41984;  2 stages = 83968 -> 2 CTAs/SM.
// ===========================================================================
#define TF16 5120
#define TF8  3072
#define QSTAGE 41984
#define SMEMQ (2*QSTAGE)

// stage-relative plane offsets
#define O_XH16 0
#define O_X8H  5120
#define O_X8L  8192
#define O_QH16 11264
#define O_Q8H  16384
#define O_Q8L  19456
#define O_KH16 22528
#define O_K8H  27648
#define O_K8L  30720
#define O_VH16 33792
#define O_V8H  38912

__global__ __launch_bounds__(128, 2)
void gemm_qkv(const __half* __restrict__ xh16, const uint8_t* __restrict__ x8h,
              const uint8_t* __restrict__ x8l,
              const __half* __restrict__ Wqh16, const uint8_t* __restrict__ Wq8h,
              const uint8_t* __restrict__ Wq8l,
              const __half* __restrict__ Wkh16, const uint8_t* __restrict__ Wk8h,
              const uint8_t* __restrict__ Wk8l,
              const __half* __restrict__ Wvh16, const uint8_t* __restrict__ Wv8h,
              const float* __restrict__ bq, const float* __restrict__ bk,
              const float* __restrict__ bv,
              float* __restrict__ Qf, float* __restrict__ Kf, float* __restrict__ Vf,
              __half* __restrict__ Qh, __half* __restrict__ Kh)
{
    extern __shared__ __align__(128) char dsm[];
    const int tid = threadIdx.x;
    const int wid = tid >> 5, lane = tid & 31;
    const int warp_m = wid & 1, warp_n = wid >> 1;
    const int m0 = blockIdx.y * 64, n0 = blockIdx.x * 64;

    const __half* pf16[4] = {
        xh16 + (size_t)m0 * DD, Wqh16 + (size_t)n0 * DD,
        Wkh16 + (size_t)n0 * DD, Wvh16 + (size_t)n0 * DD };
    const uint8_t* pf8[7] = {
        x8h + (size_t)m0 * DD,  x8l + (size_t)m0 * DD,
        Wq8h + (size_t)n0 * DD, Wq8l + (size_t)n0 * DD,
        Wk8h + (size_t)n0 * DD, Wk8l + (size_t)n0 * DD,
        Wv8h + (size_t)n0 * DD };
    const int of16[4] = {O_XH16, O_QH16, O_KH16, O_VH16};
    const int of8[7]  = {O_X8H, O_X8L, O_Q8H, O_Q8L, O_K8H, O_K8L, O_V8H};

    const uint32_t sb = s2u(dsm);

    // per chunk: f16 4 tiles x 256 CP16 = 1024;  fp8 7 tiles x 128 = 896; tot 1920
    auto issue = [&](int c, int s){
        const int kc0 = c * 32;
        const uint32_t st = sb + s * QSTAGE;
        #pragma unroll
        for (int i = 0; i < 15; i++){
            int idx = tid + i * 128;
            if (idx < 1024){
                int t = idx >> 8, rem = idx & 255;
                int r = rem >> 2, q = rem & 3;
                CP16(st + of16[t] + r * 80 + q * 16,
                     pf16[t] + (size_t)r * DD + kc0 + q * 8);
            } else {
                int j = idx - 1024;
                int t = j >> 7, rem = j & 127;
                int r = rem >> 1, q = rem & 1;
                CP16(st + of8[t] + r * 48 + q * 16,
                     pf8[t] + (size_t)r * DD + kc0 + q * 16);
            }
        }
        CP_COMMIT();
    };

    const int lrow = lane & 15, lph = lane >> 4;
    // f16 frag bases (pitch 80)
    uint32_t aA16[2], aB16[2];
    #pragma unroll
    for (int f = 0; f < 2; f++)
        aA16[f] = sb + (warp_m*32 + f*16 + lrow) * 80 + lph * 16;
    #pragma unroll
    for (int p = 0; p < 2; p++)
        aB16[p] = sb + (warp_n*32 + p*16 + lrow) * 80 + lph * 16;
    // fp8 frag bases (pitch 48)
    uint32_t aA8[2], aB8[2];
    #pragma unroll
    for (int f = 0; f < 2; f++)
        aA8[f] = sb + (warp_m*32 + f*16 + lrow) * 48 + lph * 16;
    #pragma unroll
    for (int p = 0; p < 2; p++)
        aB8[p] = sb + (warp_n*32 + p*16 + lrow) * 48 + lph * 16;

    float accQ[2][4][4], accK[2][4][4], accV[2][4][4];
    float crQ[2][4][4],  crK[2][4][4],  crV[2][4][4];
    #pragma unroll
    for (int f = 0; f < 2; f++)
        #pragma unroll
        for (int b = 0; b < 4; b++)
            #pragma unroll
            for (int j = 0; j < 4; j++){
                accQ[f][b][j]=0.f; accK[f][b][j]=0.f; accV[f][b][j]=0.f;
                crQ[f][b][j]=0.f;  crK[f][b][j]=0.f;  crV[f][b][j]=0.f;
            }

    const int NC = DD / 32;
    issue(0, 0);
    issue(1, 1);

    for (int c = 0; c < NC; c++){
        if (c < NC - 1) CP_WAIT1(); else CP_WAIT0();
        __syncthreads();

        const uint32_t so = (c & 1) * QSTAGE;

        // ---- f16 hi*hi (2 k16 steps) ----
        #pragma unroll
        for (int ks = 0; ks < 2; ks++){
            const uint32_t ko = ks * 32;
            uint32_t ah[2][4], bq16[2][4], bk16[2][4], bv16[2][4];
            #pragma unroll
            for (int f = 0; f < 2; f++)
                LDSM4(ah[f][0],ah[f][1],ah[f][2],ah[f][3], aA16[f] + so + O_XH16 + ko);
            #pragma unroll
            for (int p = 0; p < 2; p++){
                LDSM4(bq16[p][0],bq16[p][1],bq16[p][2],bq16[p][3], aB16[p] + so + O_QH16 + ko);
                LDSM4(bk16[p][0],bk16[p][1],bk16[p][2],bk16[p][3], aB16[p] + so + O_KH16 + ko);
                LDSM4(bv16[p][0],bv16[p][1],bv16[p][2],bv16[p][3], aB16[p] + so + O_VH16 + ko);
            }
            #pragma unroll
            for (int f = 0; f < 2; f++)
                #pragma unroll
                for (int p = 0; p < 2; p++)
                    #pragma unroll
                    for (int nb = 0; nb < 2; nb++){
                        const int b = p*2 + nb;
                        MMAF32(accQ[f][b], ah[f][0],ah[f][1],ah[f][2],ah[f][3],
                               bq16[p][nb], bq16[p][nb+2]);
                        MMAF32(accK[f][b], ah[f][0],ah[f][1],ah[f][2],ah[f][3],
                               bk16[p][nb], bk16[p][nb+2]);
                        MMAF32(accV[f][b], ah[f][0],ah[f][1],ah[f][2],ah[f][3],
                               bv16[p][nb], bv16[p][nb+2]);
                    }
        }

        // ---- fp8 cross terms (one k32 step) ----
        {
            uint32_t a8h[2][4], a8l[2][4];
            uint32_t b8qh[2][4], b8ql[2][4], b8kh[2][4], b8kl[2][4], b8vh[2][4];
            #pragma unroll
            for (int f = 0; f < 2; f++){
                LDSM4(a8h[f][0],a8h[f][1],a8h[f][2],a8h[f][3], aA8[f] + so + O_X8H);
                LDSM4(a8l[f][0],a8l[f][1],a8l[f][2],a8l[f][3], aA8[f] + so + O_X8L);
            }
            #pragma unroll
            for (int p = 0; p < 2; p++){
                LDSM4(b8qh[p][0],b8qh[p][1],b8qh[p][2],b8qh[p][3], aB8[p] + so + O_Q8H);
                LDSM4(b8ql[p][0],b8ql[p][1],b8ql[p][2],b8ql[p][3], aB8[p] + so + O_Q8L);
                LDSM4(b8kh[p][0],b8kh[p][1],b8kh[p][2],b8kh[p][3], aB8[p] + so + O_K8H);
                LDSM4(b8kl[p][0],b8kl[p][1],b8kl[p][2],b8kl[p][3], aB8[p] + so + O_K8L);
                LDSM4(b8vh[p][0],b8vh[p][1],b8vh[p][2],b8vh[p][3], aB8[p] + so + O_V8H);
            }
            #pragma unroll
            for (int f = 0; f < 2; f++)
                #pragma unroll
                for (int p = 0; p < 2; p++)
                    #pragma unroll
                    for (int nb = 0; nb < 2; nb++){
                        const int b = p*2 + nb;
                        MMAQ8(crQ[f][b], a8l[f][0],a8l[f][1],a8l[f][2],a8l[f][3],
                              b8qh[p][nb], b8qh[p][nb+2]);
                        MMAQ8(crQ[f][b], a8h[f][0],a8h[f][1],a8h[f][2],a8h[f][3],
                              b8ql[p][nb], b8ql[p][nb+2]);
                        MMAQ8(crK[f][b], a8l[f][0],a8l[f][1],a8l[f][2],a8l[f][3],
                              b8kh[p][nb], b8kh[p][nb+2]);
                        MMAQ8(crK[f][b], a8h[f][0],a8h[f][1],a8h[f][2],a8h[f][3],
                              b8kl[p][nb], b8kl[p][nb+2]);
                        MMAQ8(crV[f][b], a8l[f][0],a8l[f][1],a8l[f][2],a8l[f][3],
                              b8vh[p][nb], b8vh[p][nb+2]);
                    }
        }

        __syncthreads();
        if (c + 2 < NC) issue(c + 2, c & 1);
    }

    // ---- epilogue: 3 passes through staging smem [64][68] ----
    float* stg = (float*)dsm;
    const int erow = lane >> 2, ecol2 = (lane & 3) * 2;

    #pragma unroll
    for (int pass = 0; pass < 3; pass++){
        float (*aF)[4][4] = (pass == 0) ? accQ : (pass == 1) ? accK : accV;
        float (*aC)[4][4] = (pass == 0) ? crQ  : (pass == 1) ? crK  : crV;
        const float* bias = (pass == 0) ? bq : (pass == 1) ? bk : bv;
        float*  Cf = (pass == 0) ? Qf : (pass == 1) ? Kf : Vf;
        __half* Ch = (pass == 0) ? Qh : (pass == 1) ? Kh : nullptr;

        #pragma unroll
        for (int f = 0; f < 2; f++)
            #pragma unroll
            for (int b = 0; b < 4; b++){
                int r  = warp_m*32 + f*16 + erow;
                int cl = warp_n*32 + (b>>1)*16 + (b&1)*8 + ecol2;
                float* hv = aF[f][b];
                float* cv = aC[f][b];
                *(float2*)&stg[r*68 + cl] =
                    make_float2(hv[0] + cv[0]*LINV, hv[1] + cv[1]*LINV);
                *(float2*)&stg[(r+8)*68 + cl] =
                    make_float2(hv[2] + cv[2]*LINV, hv[3] + cv[3]*LINV);
            }
        __syncthreads();

        #pragma unroll
        for (int i = 0; i < 32; i++){
            int idx = tid + i * 128;
            int j = idx & 63, m = idx >> 6;
            float v = stg[m*68 + j] + bias[n0 + j];
            size_t o = (size_t)(m0 + m) * DD + n0 + j;
            Cf[o] = v;
            if (pass < 2) Ch[o] = __float2half(v);
        }
        __syncthreads();
    }
}

// ===========================================================================
// gemm_s (R13 config): cheap scores, f16 acc. CTA 128x128, 256 thr = 8 warps
// (4m x 2n), warp tile 32x64, KC=64, 3-stage. 2 CTAs/SM.
// ===========================================================================
#define PITCHB 144
#define S_TILE  (128*PITCHB)
#define S_STAGE (2*S_TILE)
#define SMEMS   (3*S_STAGE)

__global__ __launch_bounds__(256, 2)
void gemm_s(const __half* __restrict__ Qh, const __half* __restrict__ Kh,
            __half* __restrict__ Sout)
{
    extern __shared__ __align__(128) char dsm[];
    const int tid = threadIdx.x;
    const int wid = tid >> 5, lane = tid & 31;
    const int warp_m = wid & 3, warp_n = wid >> 2;
    const int m0 = blockIdx.y * 128, n0 = blockIdx.x * 128, z = blockIdx.z;

    const __half* pA = Qh + (size_t)z * SS * DD + (size_t)m0 * DD;
    const __half* pB = Kh + (size_t)z * SS * DD + (size_t)n0 * DD;

    const uint32_t sb = s2u(dsm);

    auto issue = [&](int c, int s){
        const int kc0 = c * 64;
        const uint32_t st = sb + s * S_STAGE;
        #pragma unroll
        for (int i = 0; i < 8; i++){
            int idx = tid + i * 256;
            int hi = idx >> 10;
            int rem = idx & 1023;
            int r = rem >> 3, q = rem & 7;
            CP16(st + hi * S_TILE + r * PITCHB + q * 16,
                 (hi ? pB : pA) + (size_t)r * DD + kc0 + q * 8);
        }
        CP_COMMIT();
    };

    const int lrow = lane & 15, lph = lane >> 4;
    uint32_t aA[2], aB[4];
    #pragma unroll
    for (int f = 0; f < 2; f++)
        aA[f] = sb + (warp_m*32 + f*16 + lrow) * PITCHB + lph * 16;
    #pragma unroll
    for (int p = 0; p < 4; p++)
        aB[p] = sb + S_TILE + (warp_n*64 + p*16 + lrow) * PITCHB + lph * 16;

    uint32_t accl[2][8][2];
    #pragma unroll
    for (int f = 0; f < 2; f++)
        #pragma unroll
        for (int b = 0; b < 8; b++){
            accl[f][b][0] = 0u; accl[f][b][1] = 0u;
        }

    const int NC = DD / 64;
    issue(0, 0);
    issue(1, 1);

    for (int c = 0; c < NC; c++){
        if (c < NC - 1) CP_WAIT1(); else CP_WAIT0();
        __syncthreads();
        if (c + 2 < NC) issue(c + 2, (c + 2) % 3);

        const uint32_t so = (c % 3) * S_STAGE;
        #pragma unroll
        for (int ks = 0; ks < 4; ks++){
            const uint32_t ko = ks * 32;
            uint32_t ah[2][4], bh[4][4];
            #pragma unroll
            for (int f = 0; f < 2; f++)
                LDSM4(ah[f][0],ah[f][1],ah[f][2],ah[f][3], aA[f] + so + ko);
            #pragma unroll
            for (int p = 0; p < 4; p++)
                LDSM4(bh[p][0],bh[p][1],bh[p][2],bh[p][3], aB[p] + so + ko);
            #pragma unroll
            for (int f = 0; f < 2; f++)
                #pragma unroll
                for (int p = 0; p < 4; p++)
                    #pragma unroll
                    for (int nb = 0; nb < 2; nb++)
                        MMAF16(accl[f][p*2+nb], ah[f][0],ah[f][1],ah[f][2],ah[f][3],
                               bh[p][nb], bh[p][nb+2]);
        }
    }
    __syncthreads();

    uint32_t* stg = (uint32_t*)dsm;
    const int erow = lane >> 2, ecol = lane & 3;
    #pragma unroll
    for (int f = 0; f < 2; f++)
        #pragma unroll
        for (int p = 0; p < 4; p++)
            #pragma unroll
            for (int nb = 0; nb < 2; nb++){
                int r  = warp_m*32 + f*16 + erow;
                int c2 = (warp_n*64 + p*16 + nb*8) / 2 + ecol;
                uint32_t* lr = accl[f][p*2+nb];
                stg[r*66 + c2]     = lr[0];
                stg[(r+8)*66 + c2] = lr[1];
            }
    __syncthreads();

    #pragma unroll
    for (int i = 0; i < 32; i++){
        int idx = tid + i * 256;
        int j2 = idx & 63, m = idx >> 6;
        ((uint32_t*)Sout)[((size_t)z * SS * SS + (size_t)(m0 + m) * SS + n0) / 2 + j2] =
            stg[m*66 + j2];
    }
}

// ---------------------------------------------------------------------------
// conv_x: fp32 x -> f16 hi plane + fp8 hi plane + fp8 scaled-residual plane
// ---------------------------------------------------------------------------
__global__ __launch_bounds__(256)
void conv_x(const float* __restrict__ in)
{
    int i = blockIdx.x * 256 + threadIdx.x;
    float4 v = ((const float4*)in)[i];
    float vv[4] = {v.x, v.y, v.z, v.w};
    __half h[4]; uint8_t e8h[4], e8l[4];
    #pragma unroll
    for (int k = 0; k < 4; k++){
        h[k] = __float2half(vv[k]);
        e8h[k] = f2e4m3(vv[k]);
        e8l[k] = f2e4m3((vv[k] - __half2float(h[k])) * LSCALE);
    }
    ((__half2*)g_xh)[i*2+0] = __halves2half2(h[0], h[1]);
    ((__half2*)g_xh)[i*2+1] = __halves2half2(h[2], h[3]);
    uint32_t p8h = e8h[0] | (e8h[1]<<8) | (e8h[2]<<16) | (e8h[3]<<24);
    uint32_t p8l = e8l[0] | (e8l[1]<<8) | (e8l[2]<<16) | (e8l[3]<<24);
    ((uint32_t*)g_x8h)[i] = p8h;
    ((uint32_t*)g_x8l)[i] = p8l;
}

__global__ __launch_bounds__(256)
void conv_w(const float* __restrict__ Wq, const float* __restrict__ Wk,
            const float* __restrict__ Wv)
{
    int i = blockIdx.x * 256 + threadIdx.x;
    int z = blockIdx.y;
    const float* in = (z == 0) ? Wq : (z == 1) ? Wk : Wv;
    float4 v = ((const float4*)in)[i];
    float vv[4] = {v.x, v.y, v.z, v.w};
    __half h[4]; uint8_t e8h[4], e8l[4];
    #pragma unroll
    for (int k = 0; k < 4; k++){
        h[k] = __float2half(vv[k]);
        e8h[k] = f2e4m3(vv[k]);
        e8l[k] = f2e4m3((vv[k] - __half2float(h[k])) * LSCALE);
    }
    __half2 H0 = __halves2half2(h[0], h[1]), H1 = __halves2half2(h[2], h[3]);
    uint32_t p8h = e8h[0] | (e8h[1]<<8) | (e8h[2]<<16) | (e8h[3]<<24);
    uint32_t p8l = e8l[0] | (e8l[1]<<8) | (e8l[2]<<16) | (e8l[3]<<24);
    if (z == 0){
        ((__half2*)g_Wqh)[i*2+0] = H0; ((__half2*)g_Wqh)[i*2+1] = H1;
        ((uint32_t*)g_Wq8h)[i] = p8h;  ((uint32_t*)g_Wq8l)[i] = p8l;
    } else if (z == 1){
        ((__half2*)g_Wkh)[i*2+0] = H0; ((__half2*)g_Wkh)[i*2+1] = H1;
        ((uint32_t*)g_Wk8h)[i] = p8h;  ((uint32_t*)g_Wk8l)[i] = p8l;
    } else {
        ((__half2*)g_Wvh)[i*2+0] = H0; ((__half2*)g_Wvh)[i*2+1] = H1;
        ((uint32_t*)g_Wv8h)[i] = p8h;
    }
}

// ---------------------------------------------------------------------------
// Fused softmax-select-refine-gather. One CTA (256 thr) per query row.
// ---------------------------------------------------------------------------
__global__ __launch_bounds__(256)
void attn_k(const float* __restrict__ Q, const float* __restrict__ K,
            const float* __restrict__ V, float* __restrict__ out)
{
    const int g = blockIdx.x;
    const int b = g >> 11;
    const __half2* srow = (const __half2*)(g_S + (size_t)g * SS);
    const int tid = threadIdx.x;
    const int lane = tid & 31, w = tid >> 5;

    __shared__ float red[8];
    __shared__ int   s_idx[SS];
    __shared__ float s_p[SS];
    __shared__ int   s_cnt;

    float lv[8];
    float mx = -3.4e38f;
    #pragma unroll
    for (int i = 0; i < 4; i++){
        float2 v2 = __half22float2(srow[tid + i*256]);
        lv[2*i] = v2.x; lv[2*i+1] = v2.y;
        mx = fmaxf(mx, fmaxf(v2.x, v2.y));
    }
    #pragma unroll
    for (int o = 16; o; o >>= 1) mx = fmaxf(mx, __shfl_xor_sync(0xffffffffu, mx, o));
    if (lane == 0) red[w] = mx;
    if (tid == 0) s_cnt = 0;
    __syncthreads();
    float m = red[0];
    #pragma unroll
    for (int i = 1; i < 8; i++) m = fmaxf(m, red[i]);

    const float thr = m - 15.0f;
    #pragma unroll
    for (int i = 0; i < 4; i++){
        if (lv[2*i] > thr){
            int pos = atomicAdd(&s_cnt, 1);
            s_idx[pos] = 2*(tid + i*256);
        }
        if (lv[2*i+1] > thr){
            int pos = atomicAdd(&s_cnt, 1);
            s_idx[pos] = 2*(tid + i*256) + 1;
        }
    }
    __syncthreads();
    const int nc = s_cnt;

    const float* qr = Q + (size_t)g * DD;
    for (int j = w; j < nc; j += 8){
        const float* kr = K + ((size_t)(b << 11) + s_idx[j]) * DD;
        float a = 0.f;
        #pragma unroll 8
        for (int d = lane; d < DD; d += 32) a += qr[d] * kr[d];
        #pragma unroll
        for (int o = 16; o; o >>= 1) a += __shfl_xor_sync(0xffffffffu, a, o);
        if (lane == 0) s_p[j] = expf(a - m);
    }
    __syncthreads();

    float Z = 0.f;
    for (int j = 0; j < nc; j++) Z += s_p[j];
    const float invZ = 1.0f / Z;

    float4 o4 = make_float4(0.f, 0.f, 0.f, 0.f);
    for (int j = 0; j < nc; j++){
        const float pj = s_p[j];
        float4 vv = ((const float4*)(V + ((size_t)(b << 11) + s_idx[j]) * DD))[tid];
        o4.x += pj * vv.x; o4.y += pj * vv.y;
        o4.z += pj * vv.z; o4.w += pj * vv.w;
    }
    o4.x *= invZ; o4.y *= invZ; o4.z *= invZ; o4.w *= invZ;
    ((float4*)(out + (size_t)g * DD))[tid] = o4;
}

// ---------------------------------------------------------------------------
extern "C" void kernel_launch(void* const* d_in, const int* in_sizes, int n_in,
                              void* d_out, int out_size)
{
    const float* x  = (const float*)d_in[0];
    const float* Wq = (const float*)d_in[1];
    const float* bq = (const float*)d_in[2];
    const float* Wk = (const float*)d_in[3];
    const float* bk = (const float*)d_in[4];
    const float* Wv = (const float*)d_in[5];
    const float* bv = (const float*)d_in[6];
    float* out = (float*)d_out;

    __half *xh,*Wqh,*Wkh,*Wvh,*Qh,*Kh,*Sp;
    uint8_t *x8h,*x8l,*Wq8h,*Wq8l,*Wk8h,*Wk8l,*Wv8h;
    float *Qf,*Kf,*Vf;
    cudaGetSymbolAddress((void**)&xh,   g_xh);
    cudaGetSymbolAddress((void**)&x8h,  g_x8h);  cudaGetSymbolAddress((void**)&x8l,  g_x8l);
    cudaGetSymbolAddress((void**)&Wqh,  g_Wqh);
    cudaGetSymbolAddress((void**)&Wq8h, g_Wq8h); cudaGetSymbolAddress((void**)&Wq8l, g_Wq8l);
    cudaGetSymbolAddress((void**)&Wkh,  g_Wkh);
    cudaGetSymbolAddress((void**)&Wk8h, g_Wk8h); cudaGetSymbolAddress((void**)&Wk8l, g_Wk8l);
    cudaGetSymbolAddress((void**)&Wvh,  g_Wvh);
    cudaGetSymbolAddress((void**)&Wv8h, g_Wv8h);
    cudaGetSymbolAddress((void**)&Qf,   g_Qf);   cudaGetSymbolAddress((void**)&Kf,   g_Kf);
    cudaGetSymbolAddress((void**)&Vf,   g_Vf);
    cudaGetSymbolAddress((void**)&Qh,   g_Qh);   cudaGetSymbolAddress((void**)&Kh,   g_Kh);
    cudaGetSymbolAddress((void**)&Sp,   g_S);

    cudaFuncSetAttribute(gemm_qkv, cudaFuncAttributeMaxDynamicSharedMemorySize, SMEMQ);
    cudaFuncSetAttribute(gemm_s,   cudaFuncAttributeMaxDynamicSharedMemorySize, SMEMS);

    // 0) splits
    conv_x<<<M1*DD/4/256, 256>>>(x);
    conv_w<<<dim3(DD*DD/4/256, 3), 256>>>(Wq, Wk, Wv);

    // 1) merged Q+K+V projections with fp8 cross terms, CTA tile 64x64
    dim3 gp(DD/64, M1/64, 1);
    gemm_qkv<<<gp, 128, SMEMQ>>>(xh, x8h, x8l,
                                 Wqh, Wq8h, Wq8l,
                                 Wkh, Wk8h, Wk8l,
                                 Wvh, Wv8h,
                                 bq, bk, bv, Qf, Kf, Vf, Qh, Kh);

    // 2) cheap scores (f16 accumulation)
    dim3 gs(SS/128, SS/128, BB);
    gemm_s<<<gs, 256, SMEMS>>>(Qh, Kh, Sp);

    // 3) fused softmax-select-refine-gather
    attn_k<<<M1, 256>>>(Qf, Kf, Vf, out);
}

// round 16
// speedup vs baseline: 1.2236x; 1.2236x over previous
#include <cuda_runtime.h>
#include <cuda_fp16.h>
#include <stdint.h>
#include <math.h>

#define BB 4
#define SS 2048
#define DD 1024
#define M1 (BB*SS)

#define LSCALE 2048.0f
#define LINV   (1.0f/2048.0f)

// ---------------------------------------------------------------------------
// Scratch (device globals).
// ---------------------------------------------------------------------------
__device__ __half g_xh [(size_t)M1*DD],  g_xl [(size_t)M1*DD];
__device__ __half g_Wqh[(size_t)DD*DD],  g_Wql[(size_t)DD*DD];
__device__ __half g_Wkh[(size_t)DD*DD],  g_Wkl[(size_t)DD*DD];
__device__ __half g_Wvh[(size_t)DD*DD],  g_Wvl[(size_t)DD*DD];
__device__ float  g_Qf [(size_t)M1*DD];
__device__ float  g_Kf [(size_t)M1*DD];
__device__ float  g_Vf [(size_t)M1*DD];
__device__ __half g_Qh [(size_t)M1*DD];
__device__ __half g_Kh [(size_t)M1*DD];
__device__ __half g_S  [(size_t)BB*SS*SS];

// ---------------------------------------------------------------------------
__device__ __forceinline__ uint32_t s2u(const void* p){
    uint32_t a;
    asm("{ .reg .u64 t; cvta.to.shared.u64 t, %1; cvt.u32.u64 %0, t; }" : "=r"(a) : "l"(p));
    return a;
}
__device__ __forceinline__ void split2h(float v, __half& h, __half& l){
    h = __float2half(v);
    l = __float2half((v - __half2float(h)) * LSCALE);
}

#define LDSM4(r0,r1,r2,r3,a) \
    asm volatile("ldmatrix.sync.aligned.m8n8.x4.shared.b16 {%0,%1,%2,%3}, [%4];" \
        : "=r"(r0),"=r"(r1),"=r"(r2),"=r"(r3) : "r"(a))

#define MMAF32(c,a0,a1,a2,a3,b0,b1) \
    asm volatile("mma.sync.aligned.m16n8k16.row.col.f32.f16.f16.f32 " \
        "{%0,%1,%2,%3},{%4,%5,%6,%7},{%8,%9},{%0,%1,%2,%3};" \
        : "+f"((c)[0]),"+f"((c)[1]),"+f"((c)[2]),"+f"((c)[3]) \
        : "r"(a0),"r"(a1),"r"(a2),"r"(a3),"r"(b0),"r"(b1))

#define MMAF16(c,a0,a1,a2,a3,b0,b1) \
    asm volatile("mma.sync.aligned.m16n8k16.row.col.f16.f16.f16.f16 " \
        "{%0,%1},{%2,%3,%4,%5},{%6,%7},{%0,%1};" \
        : "+r"((c)[0]),"+r"((c)[1]) \
        : "r"(a0),"r"(a1),"r"(a2),"r"(a3),"r"(b0),"r"(b1))

#define CP16(dst,src) \
    asm volatile("cp.async.cg.shared.global [%0], [%1], 16;" :: "r"(dst), "l"(src) : "memory")
#define CP_COMMIT() asm volatile("cp.async.commit_group;" ::: "memory")
#define CP_WAIT1()  asm volatile("cp.async.wait_group 1;" ::: "memory")
#define CP_WAIT0()  asm volatile("cp.async.wait_group 0;" ::: "memory")

#define PITCHB 144      // 128B data + 16B pad per row (64 halfs)

// ===========================================================================
// gemm_qkv: CTA tile 128x64, 256 thr = 8 warps (4m x 2n), warp tile 32x32,
// KC=64, 2-stage cp.async. smem = 108 KB -> 2 CTAs/SM.
//   z=0: Q (3-product)  z=1: K (3-product)  z=2: V (2-product)
// ===========================================================================
#define QA_TILE (128*PITCHB)             // 18432
#define QB_TILE (64*PITCHB)              // 9216
#define Q_STAGE (2*QA_TILE + 2*QB_TILE)  // 55296
#define SMEMQ   (2*Q_STAGE)              // 110592

__global__ __launch_bounds__(256, 2)
void gemm_qkv(const __half* __restrict__ xh, const __half* __restrict__ xl,
              const __half* __restrict__ Wqh, const __half* __restrict__ Wql,
              const __half* __restrict__ Wkh, const __half* __restrict__ Wkl,
              const __half* __restrict__ Wvh, const __half* __restrict__ Wvl,
              const float* __restrict__ bq, const float* __restrict__ bk,
              const float* __restrict__ bv,
              float* __restrict__ Qf, float* __restrict__ Kf, float* __restrict__ Vf,
              __half* __restrict__ Qh, __half* __restrict__ Kh)
{
    extern __shared__ __align__(128) char dsm[];
    const int tid = threadIdx.x;
    const int wid = tid >> 5, lane = tid & 31;
    const int warp_m = wid & 3, warp_n = wid >> 2;     // 4 x 2
    const int m0 = blockIdx.y * 128, n0 = blockIdx.x * 64;
    const int z = blockIdx.z;
    const bool p3 = (z != 2);

    const __half* Bh_ = (z == 0) ? Wqh : (z == 1) ? Wkh : Wvh;
    const __half* Bl_ = (z == 0) ? Wql : (z == 1) ? Wkl : Wvl;
    const float*  bias = (z == 0) ? bq : (z == 1) ? bk : bv;
    float* Cf  = (z == 0) ? Qf : (z == 1) ? Kf : Vf;
    __half* Ch = (z == 0) ? Qh : (z == 1) ? Kh : nullptr;

    const __half* pA0 = xh + (size_t)m0 * DD;
    const __half* pA1 = xl + (size_t)m0 * DD;
    const __half* pB0 = Bh_ + (size_t)n0 * DD;
    const __half* pB1 = Bl_ + (size_t)n0 * DD;

    const uint32_t sb = s2u(dsm);

    auto issue = [&](int c, int s){
        const int kc0 = c * 64;
        const uint32_t st = sb + s * Q_STAGE;
        #pragma unroll
        for (int i = 0; i < 12; i++){
            int idx = tid + i * 256;
            if (idx < 2048){
                int t = idx >> 10;               // 0=Ah 1=Al
                int rem = idx & 1023;
                int r = rem >> 3, q = rem & 7;
                CP16(st + t * QA_TILE + r * PITCHB + q * 16,
                     (t ? pA1 : pA0) + (size_t)r * DD + kc0 + q * 8);
            } else {
                int rem2 = idx - 2048;
                int t2 = rem2 >> 9;              // 0=Bh 1=Bl
                if (t2 == 1 && !p3) continue;
                int rem = rem2 & 511;
                int r = rem >> 3, q = rem & 7;
                CP16(st + 2*QA_TILE + t2 * QB_TILE + r * PITCHB + q * 16,
                     (t2 ? pB1 : pB0) + (size_t)r * DD + kc0 + q * 8);
            }
        }
        CP_COMMIT();
    };

    const int lrow = lane & 15, lph = lane >> 4;
    uint32_t aA[2], aB[2];
    #pragma unroll
    for (int f = 0; f < 2; f++)
        aA[f] = sb + (warp_m*32 + f*16 + lrow) * PITCHB + lph * 16;
    #pragma unroll
    for (int p = 0; p < 2; p++)
        aB[p] = sb + 2*QA_TILE + (warp_n*32 + p*16 + lrow) * PITCHB + lph * 16;

    float acc[2][4][4];
    uint32_t accl[2][4][2];
    #pragma unroll
    for (int f = 0; f < 2; f++)
        #pragma unroll
        for (int b = 0; b < 4; b++){
            #pragma unroll
            for (int j = 0; j < 4; j++) acc[f][b][j] = 0.f;
            accl[f][b][0] = 0u; accl[f][b][1] = 0u;
        }

    const int NC = DD / 64;
    issue(0, 0);
    issue(1, 1);

    for (int c = 0; c < NC; c++){
        if (c < NC - 1) CP_WAIT1(); else CP_WAIT0();
        __syncthreads();

        const uint32_t so = (c & 1) * Q_STAGE;
        #pragma unroll
        for (int ks = 0; ks < 4; ks++){
            const uint32_t ko = ks * 32;
            uint32_t ah[2][4], al[2][4], bh[2][4], bl[2][4];
            #pragma unroll
            for (int f = 0; f < 2; f++){
                LDSM4(ah[f][0],ah[f][1],ah[f][2],ah[f][3], aA[f] + so + ko);
                LDSM4(al[f][0],al[f][1],al[f][2],al[f][3], aA[f] + so + ko + QA_TILE);
            }
            #pragma unroll
            for (int p = 0; p < 2; p++){
                LDSM4(bh[p][0],bh[p][1],bh[p][2],bh[p][3], aB[p] + so + ko);
                if (p3)
                    LDSM4(bl[p][0],bl[p][1],bl[p][2],bl[p][3], aB[p] + so + ko + QB_TILE);
            }
            #pragma unroll
            for (int f = 0; f < 2; f++)
                #pragma unroll
                for (int p = 0; p < 2; p++)
                    #pragma unroll
                    for (int nb = 0; nb < 2; nb++){
                        float* cc = acc[f][p*2+nb];
                        uint32_t* cl = accl[f][p*2+nb];
                        MMAF32(cc, ah[f][0],ah[f][1],ah[f][2],ah[f][3],
                               bh[p][nb], bh[p][nb+2]);
                        MMAF16(cl, al[f][0],al[f][1],al[f][2],al[f][3],
                               bh[p][nb], bh[p][nb+2]);
                        if (p3)
                            MMAF16(cl, ah[f][0],ah[f][1],ah[f][2],ah[f][3],
                                   bl[p][nb], bl[p][nb+2]);
                    }
        }
        __syncthreads();
        if (c + 2 < NC) issue(c + 2, c & 1);
    }

    // ---- epilogue: merge -> staging smem [128][68] -> global ----
    float* stg = (float*)dsm;
    const int erow = lane >> 2, ecol2 = (lane & 3) * 2;
    #pragma unroll
    for (int f = 0; f < 2; f++)
        #pragma unroll
        for (int p = 0; p < 2; p++)
            #pragma unroll
            for (int nb = 0; nb < 2; nb++){
                int r  = warp_m*32 + f*16 + erow;
                int cl = warp_n*32 + p*16 + nb*8 + ecol2;
                float* cc = acc[f][p*2+nb];
                uint32_t* lr = accl[f][p*2+nb];
                float2 w0 = __half22float2(*reinterpret_cast<__half2*>(&lr[0]));
                float2 w1 = __half22float2(*reinterpret_cast<__half2*>(&lr[1]));
                *(float2*)&stg[r*68 + cl] =
                    make_float2(cc[0] + w0.x*LINV, cc[1] + w0.y*LINV);
                *(float2*)&stg[(r+8)*68 + cl] =
                    make_float2(cc[2] + w1.x*LINV, cc[3] + w1.y*LINV);
            }
    __syncthreads();

    #pragma unroll
    for (int i = 0; i < 32; i++){
        int idx = tid + i * 256;
        int j = idx & 63, m = idx >> 6;
        float v = stg[m*68 + j] + bias[n0 + j];
        size_t o = (size_t)(m0 + m) * DD + n0 + j;
        Cf[o] = v;
        if (p3) Ch[o] = __float2half(v);
    }
}

// ===========================================================================
// gemm_s: cheap scores with pure f16 accumulation.
// CTA 128x128, 256 thr = 8 warps (4m x 2n), warp tile 32x64, KC=64,
// 3-stage cp.async, hi planes only. 2 CTAs/SM.
// ===========================================================================
#define S_TILE  (128*PITCHB)          // 18432
#define S_STAGE (2*S_TILE)            // 36864
#define SMEMS   (3*S_STAGE)           // 110592

__global__ __launch_bounds__(256, 2)
void gemm_s(const __half* __restrict__ Qh, const __half* __restrict__ Kh,
            __half* __restrict__ Sout)
{
    extern __shared__ __align__(128) char dsm[];
    const int tid = threadIdx.x;
    const int wid = tid >> 5, lane = tid & 31;
    const int warp_m = wid & 3, warp_n = wid >> 2;
    const int m0 = blockIdx.y * 128, n0 = blockIdx.x * 128, z = blockIdx.z;

    const __half* pA = Qh + (size_t)z * SS * DD + (size_t)m0 * DD;
    const __half* pB = Kh + (size_t)z * SS * DD + (size_t)n0 * DD;

    const uint32_t sb = s2u(dsm);

    auto issue = [&](int c, int s){
        const int kc0 = c * 64;
        const uint32_t st = sb + s * S_STAGE;
        #pragma unroll
        for (int i = 0; i < 8; i++){
            int idx = tid + i * 256;
            int hi = idx >> 10;
            int rem = idx & 1023;
            int r = rem >> 3, q = rem & 7;
            CP16(st + hi * S_TILE + r * PITCHB + q * 16,
                 (hi ? pB : pA) + (size_t)r * DD + kc0 + q * 8);
        }
        CP_COMMIT();
    };

    const int lrow = lane & 15, lph = lane >> 4;
    uint32_t aA[2], aB[4];
    #pragma unroll
    for (int f = 0; f < 2; f++)
        aA[f] = sb + (warp_m*32 + f*16 + lrow) * PITCHB + lph * 16;
    #pragma unroll
    for (int p = 0; p < 4; p++)
        aB[p] = sb + S_TILE + (warp_n*64 + p*16 + lrow) * PITCHB + lph * 16;

    uint32_t accl[2][8][2];
    #pragma unroll
    for (int f = 0; f < 2; f++)
        #pragma unroll
        for (int b = 0; b < 8; b++){
            accl[f][b][0] = 0u; accl[f][b][1] = 0u;
        }

    const int NC = DD / 64;
    issue(0, 0);
    issue(1, 1);

    for (int c = 0; c < NC; c++){
        if (c < NC - 1) CP_WAIT1(); else CP_WAIT0();
        __syncthreads();
        if (c + 2 < NC) issue(c + 2, (c + 2) % 3);

        const uint32_t so = (c % 3) * S_STAGE;
        #pragma unroll
        for (int ks = 0; ks < 4; ks++){
            const uint32_t ko = ks * 32;
            uint32_t ah[2][4], bh[4][4];
            #pragma unroll
            for (int f = 0; f < 2; f++)
                LDSM4(ah[f][0],ah[f][1],ah[f][2],ah[f][3], aA[f] + so + ko);
            #pragma unroll
            for (int p = 0; p < 4; p++)
                LDSM4(bh[p][0],bh[p][1],bh[p][2],bh[p][3], aB[p] + so + ko);
            #pragma unroll
            for (int f = 0; f < 2; f++)
                #pragma unroll
                for (int p = 0; p < 4; p++)
                    #pragma unroll
                    for (int nb = 0; nb < 2; nb++)
                        MMAF16(accl[f][p*2+nb], ah[f][0],ah[f][1],ah[f][2],ah[f][3],
                               bh[p][nb], bh[p][nb+2]);
        }
    }
    __syncthreads();

    // ---- epilogue: half2 accumulators -> staging smem -> fp16 global ----
    uint32_t* stg = (uint32_t*)dsm;
    const int erow = lane >> 2, ecol = lane & 3;
    #pragma unroll
    for (int f = 0; f < 2; f++)
        #pragma unroll
        for (int p = 0; p < 4; p++)
            #pragma unroll
            for (int nb = 0; nb < 2; nb++){
                int r  = warp_m*32 + f*16 + erow;
                int c2 = (warp_n*64 + p*16 + nb*8) / 2 + ecol;
                uint32_t* lr = accl[f][p*2+nb];
                stg[r*66 + c2]     = lr[0];
                stg[(r+8)*66 + c2] = lr[1];
            }
    __syncthreads();

    #pragma unroll
    for (int i = 0; i < 32; i++){
        int idx = tid + i * 256;
        int j2 = idx & 63, m = idx >> 6;
        ((uint32_t*)Sout)[((size_t)z * SS * SS + (size_t)(m0 + m) * SS + n0) / 2 + j2] =
            stg[m*66 + j2];
    }
}

// ---------------------------------------------------------------------------
__global__ __launch_bounds__(256)
void conv_x(const float* __restrict__ in, __half* __restrict__ oh,
            __half* __restrict__ ol)
{
    int i = blockIdx.x * 256 + threadIdx.x;
    float4 v = ((const float4*)in)[i];
    __half h0,h1,h2,h3,l0,l1,l2,l3;
    split2h(v.x,h0,l0); split2h(v.y,h1,l1); split2h(v.z,h2,l2); split2h(v.w,h3,l3);
    __half2* H = (__half2*)oh;  __half2* L = (__half2*)ol;
    H[i*2+0] = __halves2half2(h0,h1);  H[i*2+1] = __halves2half2(h2,h3);
    L[i*2+0] = __halves2half2(l0,l1);  L[i*2+1] = __halves2half2(l2,l3);
}

__global__ __launch_bounds__(256)
void conv_w(const float* __restrict__ Wq, const float* __restrict__ Wk,
            const float* __restrict__ Wv)
{
    int i = blockIdx.x * 256 + threadIdx.x;
    int z = blockIdx.y;
    const float* in = (z == 0) ? Wq : (z == 1) ? Wk : Wv;
    __half* oh = (z == 0) ? g_Wqh : (z == 1) ? g_Wkh : g_Wvh;
    __half* ol = (z == 0) ? g_Wql : (z == 1) ? g_Wkl : g_Wvl;
    float4 v = ((const float4*)in)[i];
    __half h0,h1,h2,h3,l0,l1,l2,l3;
    split2h(v.x,h0,l0); split2h(v.y,h1,l1); split2h(v.z,h2,l2); split2h(v.w,h3,l3);
    __half2* H = (__half2*)oh;  __half2* L = (__half2*)ol;
    H[i*2+0] = __halves2half2(h0,h1);  H[i*2+1] = __halves2half2(h2,h3);
    L[i*2+0] = __halves2half2(l0,l1);  L[i*2+1] = __halves2half2(l2,l3);
}

// ---------------------------------------------------------------------------
// Fused softmax-select-refine-gather. One CTA (256 thr) per query row.
// ---------------------------------------------------------------------------
__global__ __launch_bounds__(256)
void attn_k(const float* __restrict__ Q, const float* __restrict__ K,
            const float* __restrict__ V, float* __restrict__ out)
{
    const int g = blockIdx.x;
    const int b = g >> 11;
    const __half2* srow = (const __half2*)(g_S + (size_t)g * SS);
    const int tid = threadIdx.x;
    const int lane = tid & 31, w = tid >> 5;

    __shared__ float red[8];
    __shared__ int   s_idx[SS];
    __shared__ float s_p[SS];
    __shared__ int   s_cnt;

    float lv[8];
    float mx = -3.4e38f;
    #pragma unroll
    for (int i = 0; i < 4; i++){
        float2 v2 = __half22float2(srow[tid + i*256]);
        lv[2*i] = v2.x; lv[2*i+1] = v2.y;
        mx = fmaxf(mx, fmaxf(v2.x, v2.y));
    }
    #pragma unroll
    for (int o = 16; o; o >>= 1) mx = fmaxf(mx, __shfl_xor_sync(0xffffffffu, mx, o));
    if (lane == 0) red[w] = mx;
    if (tid == 0) s_cnt = 0;
    __syncthreads();
    float m = red[0];
    #pragma unroll
    for (int i = 1; i < 8; i++) m = fmaxf(m, red[i]);

    const float thr = m - 15.0f;
    #pragma unroll
    for (int i = 0; i < 4; i++){
        if (lv[2*i] > thr){
            int pos = atomicAdd(&s_cnt, 1);
            s_idx[pos] = 2*(tid + i*256);
        }
        if (lv[2*i+1] > thr){
            int pos = atomicAdd(&s_cnt, 1);
            s_idx[pos] = 2*(tid + i*256) + 1;
        }
    }
    __syncthreads();
    const int nc = s_cnt;

    const float* qr = Q + (size_t)g * DD;
    for (int j = w; j < nc; j += 8){
        const float* kr = K + ((size_t)(b << 11) + s_idx[j]) * DD;
        float a = 0.f;
        #pragma unroll 8
        for (int d = lane; d < DD; d += 32) a += qr[d] * kr[d];
        #pragma unroll
        for (int o = 16; o; o >>= 1) a += __shfl_xor_sync(0xffffffffu, a, o);
        if (lane == 0) s_p[j] = expf(a - m);
    }
    __syncthreads();

    float Z = 0.f;
    for (int j = 0; j < nc; j++) Z += s_p[j];
    const float invZ = 1.0f / Z;

    float4 o4 = make_float4(0.f, 0.f, 0.f, 0.f);
    for (int j = 0; j < nc; j++){
        const float pj = s_p[j];
        float4 vv = ((const float4*)(V + ((size_t)(b << 11) + s_idx[j]) * DD))[tid];
        o4.x += pj * vv.x; o4.y += pj * vv.y;
        o4.z += pj * vv.z; o4.w += pj * vv.w;
    }
    o4.x *= invZ; o4.y *= invZ; o4.z *= invZ; o4.w *= invZ;
    ((float4*)(out + (size_t)g * DD))[tid] = o4;
}

// ---------------------------------------------------------------------------
extern "C" void kernel_launch(void* const* d_in, const int* in_sizes, int n_in,
                              void* d_out, int out_size)
{
    const float* x  = (const float*)d_in[0];
    const float* Wq = (const float*)d_in[1];
    const float* bq = (const float*)d_in[2];
    const float* Wk = (const float*)d_in[3];
    const float* bk = (const float*)d_in[4];
    const float* Wv = (const float*)d_in[5];
    const float* bv = (const float*)d_in[6];
    float* out = (float*)d_out;

    __half *xh,*xl,*Wqh,*Wql,*Wkh,*Wkl,*Wvh,*Wvl,*Qh,*Kh,*Sp;
    float *Qf,*Kf,*Vf;
    cudaGetSymbolAddress((void**)&xh,  g_xh);  cudaGetSymbolAddress((void**)&xl,  g_xl);
    cudaGetSymbolAddress((void**)&Wqh, g_Wqh); cudaGetSymbolAddress((void**)&Wql, g_Wql);
    cudaGetSymbolAddress((void**)&Wkh, g_Wkh); cudaGetSymbolAddress((void**)&Wkl, g_Wkl);
    cudaGetSymbolAddress((void**)&Wvh, g_Wvh); cudaGetSymbolAddress((void**)&Wvl, g_Wvl);
    cudaGetSymbolAddress((void**)&Qf,  g_Qf);  cudaGetSymbolAddress((void**)&Kf,  g_Kf);
    cudaGetSymbolAddress((void**)&Vf,  g_Vf);
    cudaGetSymbolAddress((void**)&Qh,  g_Qh);  cudaGetSymbolAddress((void**)&Kh,  g_Kh);
    cudaGetSymbolAddress((void**)&Sp,  g_S);

    cudaFuncSetAttribute(gemm_qkv, cudaFuncAttributeMaxDynamicSharedMemorySize, SMEMQ);
    cudaFuncSetAttribute(gemm_s,   cudaFuncAttributeMaxDynamicSharedMemorySize, SMEMS);

    // 0) splits
    conv_x<<<M1*DD/4/256, 256>>>(x, xh, xl);
    conv_w<<<dim3(DD*DD/4/256, 3), 256>>>(Wq, Wk, Wv);

    // 1) merged projections (z: 0=Q, 1=K, 2=V), CTA tile 128x64, 256 thr
    dim3 gp(DD/64, M1/128, 3);
    gemm_qkv<<<gp, 256, SMEMQ>>>(xh, xl, Wqh, Wql, Wkh, Wkl, Wvh, Wvl,
                                 bq, bk, bv, Qf, Kf, Vf, Qh, Kh);

    // 2) cheap scores (f16 accumulation)
    dim3 gs(SS/128, SS/128, BB);
    gemm_s<<<gs, 256, SMEMS>>>(Qh, Kh, Sp);

    // 3) fused softmax-select-refine-gather
    attn_k<<<M1, 256>>>(Qf, Kf, Vf, out);
}